// round 4
// baseline (speedup 1.0000x reference)
#include <cuda_runtime.h>
#include <math.h>

#define DDIM 128
#define KCODES 256
#define BM 64
#define DC 32
#define MAXB 8192   // max N/BM we support for partial buffer (N=524288 -> 8192)

// Scratch (device globals: no allocation allowed)
__device__ __align__(16) float g_en[KCODES * DDIM];      // normalized codebook
__device__ float g_part[MAXB * KCODES];                  // per-CTA prob partial sums
__device__ float g_part2[32 * KCODES];                   // stage-2 partials

// ---------------------------------------------------------------------------
// prep: e_n = e / max(||e||, 1e-12)
// ---------------------------------------------------------------------------
__global__ void prep_kernel(const float* __restrict__ emb) {
    int k = threadIdx.x;  // 256 threads, one code each
    const float* row = emb + k * DDIM;
    float ss = 0.f;
    #pragma unroll 8
    for (int d = 0; d < DDIM; d++) { float x = row[d]; ss = fmaf(x, x, ss); }
    float inv = 1.0f / fmaxf(sqrtf(ss), 1e-12f);
    #pragma unroll 8
    for (int d = 0; d < DDIM; d++) g_en[k * DDIM + d] = row[d] * inv;
}

// ---------------------------------------------------------------------------
// main: per 64-row tile — fp32 logits vs all 256 codes, argmax, softmax,
//       z_q gather, per-CTA avg_prob partials.
// Thread map: tid = ty*16+tx ; rows = ty*4..ty*4+3 ; codes = tx + 16*i
// ---------------------------------------------------------------------------
__global__ void __launch_bounds__(256, 2) main_kernel(
    const float* __restrict__ z, const float* __restrict__ emb,
    const float* __restrict__ scale_p, float* __restrict__ out, int N)
{
    __shared__ float smem[2048 + 8192];   // 40 KB
    float* sZ = smem;                     // [DC][BM]      (d-major)
    float* sE = smem + 2048;              // [DC][KCODES]  (d-major)
    float* sRed = smem + 2048;            // alias of sE: [16][KCODES]

    const int tid = threadIdx.x;
    const int tx = tid & 15;
    const int ty = tid >> 4;
    const int m0 = blockIdx.x * BM;

    float acc[4][16];
    #pragma unroll
    for (int j = 0; j < 4; j++)
        #pragma unroll
        for (int i = 0; i < 16; i++) acc[j][i] = 0.f;
    float zn[4] = {0.f, 0.f, 0.f, 0.f};

    for (int dc = 0; dc < DDIM; dc += DC) {
        // load z tile chunk: 64 rows x 32 d  (transposed into sZ[d][m])
        #pragma unroll
        for (int it = 0; it < 2; it++) {
            int idx = tid + it * 256;        // 0..511
            int m = idx >> 3;
            int q = idx & 7;
            float4 v = *(const float4*)(z + (size_t)(m0 + m) * DDIM + dc + q * 4);
            sZ[(q * 4 + 0) * BM + m] = v.x;
            sZ[(q * 4 + 1) * BM + m] = v.y;
            sZ[(q * 4 + 2) * BM + m] = v.z;
            sZ[(q * 4 + 3) * BM + m] = v.w;
        }
        // load e_n chunk: 256 codes x 32 d (transposed into sE[d][k])
        #pragma unroll
        for (int it = 0; it < 8; it++) {
            int idx = tid + it * 256;        // 0..2047
            int kk = idx >> 3;
            int q = idx & 7;
            float4 v = *(const float4*)(g_en + kk * DDIM + dc + q * 4);
            sE[(q * 4 + 0) * KCODES + kk] = v.x;
            sE[(q * 4 + 1) * KCODES + kk] = v.y;
            sE[(q * 4 + 2) * KCODES + kk] = v.z;
            sE[(q * 4 + 3) * KCODES + kk] = v.w;
        }
        __syncthreads();

        #pragma unroll
        for (int d = 0; d < DC; d++) {
            float zr[4];
            #pragma unroll
            for (int j = 0; j < 4; j++) zr[j] = sZ[d * BM + ty * 4 + j];
            float ek[16];
            #pragma unroll
            for (int i = 0; i < 16; i++) ek[i] = sE[d * KCODES + tx + 16 * i];
            #pragma unroll
            for (int j = 0; j < 4; j++) {
                zn[j] = fmaf(zr[j], zr[j], zn[j]);
                #pragma unroll
                for (int i = 0; i < 16; i++)
                    acc[j][i] = fmaf(zr[j], ek[i], acc[j][i]);
            }
        }
        __syncthreads();
    }

    // -------- epilogue --------
    const float s = *scale_p;
    const unsigned FULL = 0xFFFFFFFFu;
    float psum[16];
    #pragma unroll
    for (int i = 0; i < 16; i++) psum[i] = 0.f;

    #pragma unroll
    for (int j = 0; j < 4; j++) {
        const int m = m0 + ty * 4 + j;

        // local argmax over this thread's 16 codes (codes tx+16i increase with i,
        // strict > keeps lowest index on exact ties, matching jnp.argmax)
        float bv = acc[j][0];
        int   bi = tx;
        #pragma unroll
        for (int i = 1; i < 16; i++) {
            float v = acc[j][i];
            int   c = tx + 16 * i;
            if (v > bv) { bv = v; bi = c; }
        }
        // shuffle-reduce over the 16-lane tx group (lane bits 0..3)
        #pragma unroll
        for (int o = 1; o < 16; o <<= 1) {
            float ov = __shfl_xor_sync(FULL, bv, o);
            int   oi = __shfl_xor_sync(FULL, bi, o);
            if (ov > bv || (ov == bv && oi < bi)) { bv = ov; bi = oi; }
        }

        const float invn = 1.0f / fmaxf(sqrtf(zn[j]), 1e-12f);
        const float sc = s * invn;
        float p[16];
        float se = 0.f;
        #pragma unroll
        for (int i = 0; i < 16; i++) {
            p[i] = __expf(sc * (acc[j][i] - bv));
            se += p[i];
        }
        #pragma unroll
        for (int o = 1; o < 16; o <<= 1) se += __shfl_xor_sync(FULL, se, o);
        const float rinv = 1.0f / se;
        #pragma unroll
        for (int i = 0; i < 16; i++) psum[i] = fmaf(p[i], rinv, psum[i]);

        // outputs: index (as float) + z_q gather (16 threads copy 128 floats)
        if (tx == 0) out[(size_t)N * DDIM + m] = (float)bi;
        const float4* src = (const float4*)(emb + (size_t)bi * DDIM);
        float4* dst = (float4*)(out + (size_t)m * DDIM);
        dst[tx]      = src[tx];
        dst[tx + 16] = src[tx + 16];
    }

    // per-CTA reduction of prob partials over ty, then write fixed slot
    #pragma unroll
    for (int i = 0; i < 16; i++) sRed[ty * KCODES + tx + 16 * i] = psum[i];
    __syncthreads();
    float tot = 0.f;
    #pragma unroll
    for (int r = 0; r < 16; r++) tot += sRed[r * KCODES + tid];
    g_part[(size_t)blockIdx.x * KCODES + tid] = tot;
}

// ---------------------------------------------------------------------------
// reduce1: 32 blocks x 256 threads; block r sums 256 CTA-partials per code.
// ---------------------------------------------------------------------------
__global__ void reduce1_kernel(int nb) {
    int r = blockIdx.x;
    int k = threadIdx.x;
    float sum = 0.f;
    for (int j = 0; j < 256; j++) {
        int b = r * 256 + j;
        if (b < nb) sum += g_part[(size_t)b * KCODES + k];
    }
    g_part2[r * KCODES + k] = sum;
}

// ---------------------------------------------------------------------------
// ppl: final perplexity = exp(-sum(avg_probs * log(avg_probs + 1e-10)))
// ---------------------------------------------------------------------------
__global__ void ppl_kernel(float* __restrict__ out, float invN, size_t off) {
    int k = threadIdx.x;  // 256 threads
    float a = 0.f;
    #pragma unroll
    for (int r = 0; r < 32; r++) a += g_part2[r * KCODES + k];
    a *= invN;
    float t = -a * logf(a + 1e-10f);

    __shared__ float red[8];
    #pragma unroll
    for (int o = 16; o; o >>= 1) t += __shfl_xor_sync(0xFFFFFFFFu, t, o);
    if ((k & 31) == 0) red[k >> 5] = t;
    __syncthreads();
    if (k < 8) {
        float v = red[k];
        #pragma unroll
        for (int o = 4; o; o >>= 1) v += __shfl_xor_sync(0xFFu, v, o);
        if (k == 0) out[off] = expf(v);
    }
}

// ---------------------------------------------------------------------------
extern "C" void kernel_launch(void* const* d_in, const int* in_sizes, int n_in,
                              void* d_out, int out_size) {
    const float* z     = (const float*)d_in[0];
    const float* emb   = (const float*)d_in[1];
    const float* scale = (const float*)d_in[2];
    float* out = (float*)d_out;

    const int N = in_sizes[0] / DDIM;
    const int nb = N / BM;

    prep_kernel<<<1, 256>>>(emb);
    main_kernel<<<nb, 256>>>(z, emb, scale, out, N);
    reduce1_kernel<<<32, 256>>>(nb);
    ppl_kernel<<<1, 256>>>(out, 1.0f / (float)N, (size_t)N * DDIM + (size_t)N);
}

// round 5
// speedup vs baseline: 1.1664x; 1.1664x over previous
#include <cuda_runtime.h>
#include <math.h>

#define DDIM 128
#define KCODES 256
#define BM 64
#define DC 32
#define MAXB 8192   // max N/BM we support for partial buffer (N=524288 -> 8192)

typedef unsigned long long ull;

// Scratch (device globals: no allocation allowed)
__device__ __align__(16) float g_en[KCODES * DDIM];      // normalized codebook
__device__ float g_part[MAXB * KCODES];                  // per-CTA prob partial sums
__device__ float g_part2[32 * KCODES];                   // stage-2 partials

// packed f32x2 fma: d = a*b + d  (elementwise, exact fp32 per lane)
__device__ __forceinline__ void ffma2(ull& d, ull a, ull b) {
    asm("fma.rn.f32x2 %0, %1, %2, %0;" : "+l"(d) : "l"(a), "l"(b));
}
// duplicate a float into both halves of a b64 (alu pipe, not fma pipe)
__device__ __forceinline__ ull pack2(float x) {
    ull r; unsigned u = __float_as_uint(x);
    asm("mov.b64 %0, {%1, %1};" : "=l"(r) : "r"(u));
    return r;
}
__device__ __forceinline__ void unpack2(float& lo, float& hi, ull v) {
    unsigned a, b;
    asm("mov.b64 {%0, %1}, %2;" : "=r"(a), "=r"(b) : "l"(v));
    lo = __uint_as_float(a); hi = __uint_as_float(b);
}

// ---------------------------------------------------------------------------
// prep: e_n = e / max(||e||, 1e-12)
// ---------------------------------------------------------------------------
__global__ void prep_kernel(const float* __restrict__ emb) {
    int k = threadIdx.x;  // 256 threads, one code each
    const float* row = emb + k * DDIM;
    float ss = 0.f;
    #pragma unroll 8
    for (int d = 0; d < DDIM; d++) { float x = row[d]; ss = fmaf(x, x, ss); }
    float inv = 1.0f / fmaxf(sqrtf(ss), 1e-12f);
    #pragma unroll 8
    for (int d = 0; d < DDIM; d++) g_en[k * DDIM + d] = row[d] * inv;
}

// ---------------------------------------------------------------------------
// main: per 64-row tile — fp32 logits vs all 256 codes via packed f32x2 FMA,
//       argmax, softmax, z_q gather, per-CTA avg_prob partials.
// Thread map: tid = ty*16+tx ; rows = ty*4..ty*4+3 ;
//             codes = pairs (2tx+32i, 2tx+32i+1), i=0..7
// ---------------------------------------------------------------------------
__global__ void __launch_bounds__(256, 2) main_kernel(
    const float* __restrict__ z, const float* __restrict__ emb,
    const float* __restrict__ scale_p, float* __restrict__ out, int N)
{
    __shared__ __align__(16) float smem[2048 + 8192];   // 40 KB
    float* sZ = smem;                     // [DC][BM]      (d-major)
    float* sE = smem + 2048;              // [DC][KCODES]  (d-major)
    float* sRed = smem + 2048;            // alias of sE: [16][KCODES]

    const int tid = threadIdx.x;
    const int tx = tid & 15;
    const int ty = tid >> 4;
    const int m0 = blockIdx.x * BM;

    ull accp[4][8];                       // [row j][code pair i] packed f32x2
    #pragma unroll
    for (int j = 0; j < 4; j++)
        #pragma unroll
        for (int i = 0; i < 8; i++) accp[j][i] = 0ull;
    ull znp[4] = {0ull, 0ull, 0ull, 0ull};

    for (int dc = 0; dc < DDIM; dc += DC) {
        // load z tile chunk: 64 rows x 32 d (transposed into sZ[d][m]), coalesced
        #pragma unroll
        for (int it = 0; it < 2; it++) {
            int idx = tid + it * 256;        // 0..511
            int m = idx >> 3;
            int q = idx & 7;
            float4 v = *(const float4*)(z + (size_t)(m0 + m) * DDIM + dc + q * 4);
            sZ[(q * 4 + 0) * BM + m] = v.x;
            sZ[(q * 4 + 1) * BM + m] = v.y;
            sZ[(q * 4 + 2) * BM + m] = v.z;
            sZ[(q * 4 + 3) * BM + m] = v.w;
        }
        // load e_n chunk: 256 codes x 32 d (transposed into sE[d][k])
        #pragma unroll
        for (int it = 0; it < 8; it++) {
            int idx = tid + it * 256;        // 0..2047
            int kk = idx >> 3;
            int q = idx & 7;
            float4 v = *(const float4*)(g_en + kk * DDIM + dc + q * 4);
            sE[(q * 4 + 0) * KCODES + kk] = v.x;
            sE[(q * 4 + 1) * KCODES + kk] = v.y;
            sE[(q * 4 + 2) * KCODES + kk] = v.z;
            sE[(q * 4 + 3) * KCODES + kk] = v.w;
        }
        __syncthreads();

        #pragma unroll
        for (int d = 0; d < DC; d++) {
            ull zz[4];
            #pragma unroll
            for (int j = 0; j < 4; j++) zz[j] = pack2(sZ[d * BM + ty * 4 + j]);
            ull ek[8];
            const ull* ep = (const ull*)(sE + d * KCODES) + tx;  // pair tx+16i
            #pragma unroll
            for (int i = 0; i < 8; i++) ek[i] = ep[16 * i];      // LDS.64, imm offsets
            #pragma unroll
            for (int j = 0; j < 4; j++) {
                ffma2(znp[j], zz[j], zz[j]);
                #pragma unroll
                for (int i = 0; i < 8; i++) ffma2(accp[j][i], zz[j], ek[i]);
            }
        }
        __syncthreads();
    }

    // -------- epilogue --------
    const float s = *scale_p;
    const unsigned FULL = 0xFFFFFFFFu;
    float psum[16];
    #pragma unroll
    for (int i = 0; i < 16; i++) psum[i] = 0.f;

    #pragma unroll
    for (int j = 0; j < 4; j++) {
        const int m = m0 + ty * 4 + j;

        float a[16];
        #pragma unroll
        for (int i = 0; i < 8; i++) unpack2(a[2 * i], a[2 * i + 1], accp[j][i]);

        // local argmax; code(t) = 2tx + 32*(t>>1) + (t&1) is strictly increasing
        // in t, so strict > keeps the lowest index on ties (matches jnp.argmax)
        float bv = a[0];
        int   bi = 2 * tx;
        #pragma unroll
        for (int t = 1; t < 16; t++) {
            int c = 2 * tx + 32 * (t >> 1) + (t & 1);
            if (a[t] > bv) { bv = a[t]; bi = c; }
        }
        // shuffle-reduce over the 16-lane tx group (lane bits 0..3)
        #pragma unroll
        for (int o = 1; o < 16; o <<= 1) {
            float ov = __shfl_xor_sync(FULL, bv, o);
            int   oi = __shfl_xor_sync(FULL, bi, o);
            if (ov > bv || (ov == bv && oi < bi)) { bv = ov; bi = oi; }
        }

        float znlo, znhi;
        unpack2(znlo, znhi, znp[j]);          // both halves equal
        const float invn = 1.0f / fmaxf(sqrtf(znlo), 1e-12f);
        const float sc = s * invn;
        float p[16];
        float se = 0.f;
        #pragma unroll
        for (int t = 0; t < 16; t++) {
            p[t] = __expf(sc * (a[t] - bv));
            se += p[t];
        }
        #pragma unroll
        for (int o = 1; o < 16; o <<= 1) se += __shfl_xor_sync(FULL, se, o);
        const float rinv = 1.0f / se;
        #pragma unroll
        for (int t = 0; t < 16; t++) psum[t] = fmaf(p[t], rinv, psum[t]);

        // outputs: index (as float) + z_q gather (16 threads copy 128 floats)
        if (tx == 0) out[(size_t)N * DDIM + m] = (float)bi;
        const float4* src = (const float4*)(emb + (size_t)bi * DDIM);
        float4* dst = (float4*)(out + (size_t)m * DDIM);
        dst[tx]      = src[tx];
        dst[tx + 16] = src[tx + 16];
    }

    // per-CTA reduction of prob partials over ty, then write fixed slot
    #pragma unroll
    for (int i = 0; i < 8; i++) {
        float2 v = make_float2(psum[2 * i], psum[2 * i + 1]);
        *(float2*)(sRed + ty * KCODES + 2 * tx + 32 * i) = v;
    }
    __syncthreads();
    float tot = 0.f;
    #pragma unroll
    for (int r = 0; r < 16; r++) tot += sRed[r * KCODES + tid];
    g_part[(size_t)blockIdx.x * KCODES + tid] = tot;
}

// ---------------------------------------------------------------------------
// reduce1: 32 blocks x 256 threads; block r sums 256 CTA-partials per code.
// ---------------------------------------------------------------------------
__global__ void reduce1_kernel(int nb) {
    int r = blockIdx.x;
    int k = threadIdx.x;
    float sum = 0.f;
    for (int j = 0; j < 256; j++) {
        int b = r * 256 + j;
        if (b < nb) sum += g_part[(size_t)b * KCODES + k];
    }
    g_part2[r * KCODES + k] = sum;
}

// ---------------------------------------------------------------------------
// ppl: final perplexity = exp(-sum(avg_probs * log(avg_probs + 1e-10)))
// ---------------------------------------------------------------------------
__global__ void ppl_kernel(float* __restrict__ out, float invN, size_t off) {
    int k = threadIdx.x;  // 256 threads
    float a = 0.f;
    #pragma unroll
    for (int r = 0; r < 32; r++) a += g_part2[r * KCODES + k];
    a *= invN;
    float t = -a * logf(a + 1e-10f);

    __shared__ float red[8];
    #pragma unroll
    for (int o = 16; o; o >>= 1) t += __shfl_xor_sync(0xFFFFFFFFu, t, o);
    if ((k & 31) == 0) red[k >> 5] = t;
    __syncthreads();
    if (k < 8) {
        float v = red[k];
        #pragma unroll
        for (int o = 4; o; o >>= 1) v += __shfl_xor_sync(0xFFu, v, o);
        if (k == 0) out[off] = expf(v);
    }
}

// ---------------------------------------------------------------------------
extern "C" void kernel_launch(void* const* d_in, const int* in_sizes, int n_in,
                              void* d_out, int out_size) {
    const float* z     = (const float*)d_in[0];
    const float* emb   = (const float*)d_in[1];
    const float* scale = (const float*)d_in[2];
    float* out = (float*)d_out;

    const int N = in_sizes[0] / DDIM;
    const int nb = N / BM;

    prep_kernel<<<1, 256>>>(emb);
    main_kernel<<<nb, 256>>>(z, emb, scale, out, N);
    reduce1_kernel<<<32, 256>>>(nb);
    ppl_kernel<<<1, 256>>>(out, 1.0f / (float)N, (size_t)N * DDIM + (size_t)N);
}